// round 6
// baseline (speedup 1.0000x reference)
#include <cuda_runtime.h>
#include <cstdint>

#define NN 100000
#define EE 3200000
#define FF 10
#define HH 20
#define DP 32                 // padded row length (floats) = 128 B
#define NBLK 148
#define NTHR 512
#define NT   (NBLK * NTHR)

// ---------------- device scratch (no allocation allowed) ----------------
__device__ __align__(256) float g_x[NN * DP];    // padded input features
__device__ __align__(256) float g_h1[NN * DP];   // padding stays 0 forever
__device__ __align__(256) float g_h2[NN * DP];
__device__ __align__(256) int   g_row_ptr[NN + 1];
__device__ __align__(256) int   g_cursor[NN];    // doubles as histogram
__device__ __align__(256) int   g_col[EE];
__device__ __align__(256) int   g_bsum[NBLK];
__device__ unsigned g_bar_count;
__device__ volatile unsigned g_bar_gen;

// ---------------- software grid barrier (all blocks co-resident) -------
__device__ __forceinline__ void grid_sync() {
    __syncthreads();
    if (threadIdx.x == 0) {
        __threadfence();
        unsigned gen = g_bar_gen;
        if (atomicAdd(&g_bar_count, 1u) == NBLK - 1) {
            g_bar_count = 0;
            __threadfence();
            g_bar_gen = gen + 1;
        } else {
            while (g_bar_gen == gen) __nanosleep(64);
        }
        __threadfence();
    }
    __syncthreads();
}

// ---------------- layer: cooperative gather + distributed transform -----
// 8 lanes per node. Lane sub<LOADCH loads float4 chunk sub of each neighbor
// row (row = 1 cache line), accumulates. Transform: each lane FMAs its 4
// input dims against zero-padded weights; width-8 butterfly reduces; lanes
// 0..4 write relu chunks.
template <int DIN>
__device__ void layer_phase(const float* __restrict__ hin,
                            const float* __restrict__ Wrel,
                            const float* __restrict__ b,
                            const float* __restrict__ Wroot,
                            float* __restrict__ hout, int n,
                            float* __restrict__ sW, int gtid) {
    constexpr int LOADCH = (DIN + 3) / 4;        // 3 for FF, 5 for HH
    float* sWrel  = sW;                          // [DP*HH], zero-padded
    float* sWroot = sW + DP * HH;
    float* sb     = sW + 2 * DP * HH;
    for (int i = threadIdx.x; i < DP * HH; i += NTHR) {
        sWrel[i]  = (i < DIN * HH) ? Wrel[i]  : 0.0f;
        sWroot[i] = (i < DIN * HH) ? Wroot[i] : 0.0f;
    }
    if (threadIdx.x < HH) sb[threadIdx.x] = b[threadIdx.x];
    __syncthreads();

    const int sub = threadIdx.x & 7;
    const int grp = gtid >> 3;
    const int GSTRIDE = NT / 8;
    const int coff = sub * 4;

    for (int i = grp; __ballot_sync(0xFFFFFFFFu, i < n); i += GSTRIDE) {
        bool act = i < n;
        int beg = 0, end = 0;
        if (act) { beg = g_row_ptr[i]; end = g_row_ptr[i + 1]; }
        bool ld = act && (sub < LOADCH);
        int lim = ld ? end : beg;

        float ax = 0.0f, ay = 0.0f, az = 0.0f, aw = 0.0f;
        int e = beg;
        for (; e + 4 <= lim; e += 4) {
            int s0 = g_col[e], s1 = g_col[e + 1];
            int s2 = g_col[e + 2], s3 = g_col[e + 3];
            float4 v0 = *(const float4*)(hin + (size_t)s0 * DP + coff);
            float4 v1 = *(const float4*)(hin + (size_t)s1 * DP + coff);
            float4 v2 = *(const float4*)(hin + (size_t)s2 * DP + coff);
            float4 v3 = *(const float4*)(hin + (size_t)s3 * DP + coff);
            ax += (v0.x + v1.x) + (v2.x + v3.x);
            ay += (v0.y + v1.y) + (v2.y + v3.y);
            az += (v0.z + v1.z) + (v2.z + v3.z);
            aw += (v0.w + v1.w) + (v2.w + v3.w);
        }
        for (; e < lim; e++) {
            int s = g_col[e];
            float4 v = *(const float4*)(hin + (size_t)s * DP + coff);
            ax += v.x; ay += v.y; az += v.z; aw += v.w;
        }

        float4 xv = make_float4(0.0f, 0.0f, 0.0f, 0.0f);
        if (ld) xv = *(const float4*)(hin + (size_t)i * DP + coff);

        float po[HH];
        #pragma unroll
        for (int j = 0; j < HH; j++) po[j] = 0.0f;
        float av[4] = {ax, ay, az, aw};
        float rv[4] = {xv.x, xv.y, xv.z, xv.w};
        #pragma unroll
        for (int k = 0; k < 4; k++) {
            const float* wr = &sWrel[(4 * sub + k) * HH];
            const float* wo = &sWroot[(4 * sub + k) * HH];
            float a = av[k], r = rv[k];
            #pragma unroll
            for (int j = 0; j < HH; j++) po[j] += a * wr[j] + r * wo[j];
        }
        if (sub == 0) {                 // bias added exactly once
            #pragma unroll
            for (int j = 0; j < HH; j++) po[j] += sb[j];
        }
        #pragma unroll
        for (int off = 4; off > 0; off >>= 1) {
            #pragma unroll
            for (int j = 0; j < HH; j++)
                po[j] += __shfl_xor_sync(0xFFFFFFFFu, po[j], off);
        }
        if (act && sub < 5) {
            float4 o;
            #pragma unroll
            for (int c = 0; c < 5; c++) {
                if (sub == c) {
                    o.x = fmaxf(po[4 * c + 0], 0.0f);
                    o.y = fmaxf(po[4 * c + 1], 0.0f);
                    o.z = fmaxf(po[4 * c + 2], 0.0f);
                    o.w = fmaxf(po[4 * c + 3], 0.0f);
                }
            }
            *(float4*)(hout + (size_t)i * DP + coff) = o;
        }
    }
}

// ---------------- pool + readout fused: warp per graph ------------------
__device__ __forceinline__ int bidx(const void* p, int i, bool is64) {
    return is64 ? (int)((const long long*)p)[i] : ((const int*)p)[i];
}

__device__ void pool_readout_phase(const float* __restrict__ h,
                                   const void* __restrict__ batch, bool is64,
                                   const float* __restrict__ Wlin,
                                   const float* __restrict__ blin,
                                   float* __restrict__ out, int n, int ng,
                                   int gtid) {
    int w = gtid >> 5;
    int lane = threadIdx.x & 31;
    if (w >= ng) return;

    int lo = 0, hi = n;
    while (lo < hi) {
        int mid = (lo + hi) >> 1;
        if (bidx(batch, mid, is64) < w) lo = mid + 1; else hi = mid;
    }
    int start = lo;
    hi = n;
    while (lo < hi) {
        int mid = (lo + hi) >> 1;
        if (bidx(batch, mid, is64) <= w) lo = mid + 1; else hi = mid;
    }
    int cnt = lo - start;

    float mx = 0.0f, sm = 0.0f;   // relu >= 0: 0-init max matches reference
    if (lane < HH) {
        const float* p = h + (size_t)start * DP + lane;
        int i = 0;
        for (; i + 4 <= cnt; i += 4) {
            float v0 = p[(size_t)(i + 0) * DP];
            float v1 = p[(size_t)(i + 1) * DP];
            float v2 = p[(size_t)(i + 2) * DP];
            float v3 = p[(size_t)(i + 3) * DP];
            mx = fmaxf(mx, fmaxf(fmaxf(v0, v1), fmaxf(v2, v3)));
            sm += (v0 + v1) + (v2 + v3);
        }
        for (; i < cnt; i++) {
            float v = p[(size_t)i * DP];
            mx = fmaxf(mx, v);
            sm += v;
        }
    }
    float mean = sm / fmaxf((float)cnt, 1.0f);

    float c0 = 0.0f, c1 = 0.0f;
    if (lane < HH) {
        c0 = mx * Wlin[lane * 2 + 0] + mean * Wlin[(HH + lane) * 2 + 0];
        c1 = mx * Wlin[lane * 2 + 1] + mean * Wlin[(HH + lane) * 2 + 1];
    }
    #pragma unroll
    for (int off = 16; off > 0; off >>= 1) {
        c0 += __shfl_down_sync(0xFFFFFFFFu, c0, off);
        c1 += __shfl_down_sync(0xFFFFFFFFu, c1, off);
    }
    if (lane == 0) {
        out[w * 2 + 0] = c0 + blin[0];
        out[w * 2 + 1] = c1 + blin[1];
    }
}

// ---------------- the single fused persistent kernel --------------------
__global__ void __launch_bounds__(NTHR, 1)
fused_kernel(const float* __restrict__ x,
             const void* __restrict__ ei,
             const void* __restrict__ batch,
             const float* __restrict__ Wrel1, const float* __restrict__ b1,
             const float* __restrict__ Wroot1,
             const float* __restrict__ Wrel2, const float* __restrict__ b2,
             const float* __restrict__ Wroot2,
             const float* __restrict__ Wrel3, const float* __restrict__ b3,
             const float* __restrict__ Wroot3,
             const float* __restrict__ Wlin, const float* __restrict__ blin,
             float* __restrict__ out, int n, int nE, int ng) {
    __shared__ float sW[2 * DP * HH + HH];
    __shared__ int s_wsum[NTHR / 32];
    __shared__ int s_boff;
    int t = threadIdx.x;
    int gtid = blockIdx.x * NTHR + t;
    int lane = t & 31;
    int wid = t >> 5;

    // dtype detect: int64 ids have zero high words; P(FP) ~ 2^-4096.
    unsigned oddw = 0;
    if (t < 128) oddw = ((const unsigned*)ei)[2 * t + 1];
    bool is64 = (__syncthreads_or(oddw != 0u) == 0);

    // ---- phase 0: zero histogram + pad x into g_x ----
    for (int i = gtid; i < n; i += NT) g_cursor[i] = 0;
    for (int i = gtid; i < n * DP; i += NT) {
        int row = i / DP, col = i % DP;
        g_x[i] = (col < FF) ? x[row * FF + col] : 0.0f;
    }
    grid_sync();

    // ---- phase 1: in-degree histogram over dst ----
    if (is64) {
        const long long* e = (const long long*)ei;
        for (int k = gtid; k < nE; k += NT)
            atomicAdd(&g_cursor[(int)e[nE + k]], 1);
    } else {
        const int* e = (const int*)ei;
        for (int k = gtid; k < nE; k += NT)
            atomicAdd(&g_cursor[e[nE + k]], 1);
    }
    grid_sync();

    // ---- phase 2: per-block exclusive scan of chunk; block sums out ----
    int chunk = (n + NBLK - 1) / NBLK;          // 676 (<= 2*NTHR)
    int base = blockIdx.x * chunk;
    {
        int i0 = 2 * t, i1 = 2 * t + 1;
        int v0 = (i0 < chunk && base + i0 < n) ? g_cursor[base + i0] : 0;
        int v1 = (i1 < chunk && base + i1 < n) ? g_cursor[base + i1] : 0;
        int ts = v0 + v1;
        int sc = ts;
        #pragma unroll
        for (int off = 1; off < 32; off <<= 1) {
            int u = __shfl_up_sync(0xFFFFFFFFu, sc, off);
            if (lane >= off) sc += u;
        }
        if (lane == 31) s_wsum[wid] = sc;
        __syncthreads();
        if (wid == 0) {
            int ws = (lane < NTHR / 32) ? s_wsum[lane] : 0;
            int wsc = ws;
            #pragma unroll
            for (int off = 1; off < 32; off <<= 1) {
                int u = __shfl_up_sync(0xFFFFFFFFu, wsc, off);
                if (lane >= off) wsc += u;
            }
            if (lane < NTHR / 32) s_wsum[lane] = wsc - ws;
            if (lane == NTHR / 32 - 1) g_bsum[blockIdx.x] = wsc;
        }
        __syncthreads();
        int excl = s_wsum[wid] + (sc - ts);
        if (i0 < chunk && base + i0 < n) g_row_ptr[base + i0] = excl;
        if (i1 < chunk && base + i1 < n) g_row_ptr[base + i1] = excl + v0;
    }
    grid_sync();

    // ---- phase 3: parallel block-offset reduce; finalize row_ptr/cursor --
    {
        int v = (t < NBLK && t < (int)blockIdx.x) ? g_bsum[t] : 0;
        #pragma unroll
        for (int off = 16; off > 0; off >>= 1)
            v += __shfl_down_sync(0xFFFFFFFFu, v, off);
        if (lane == 0) s_wsum[wid] = v;
        __syncthreads();
        if (t == 0) {
            int s = 0;
            #pragma unroll
            for (int k = 0; k < NTHR / 32; k++) s += s_wsum[k];
            s_boff = s;
            if (blockIdx.x == 0) g_row_ptr[n] = nE;
        }
        __syncthreads();
        int boff = s_boff;
        for (int i = t; i < chunk; i += NTHR) {
            int gi = base + i;
            if (gi < n) {
                int vv = g_row_ptr[gi] + boff;
                g_row_ptr[gi] = vv;
                g_cursor[gi] = vv;
            }
        }
    }
    grid_sync();

    // ---- phase 4: fill col (CSR by dst, values = src) ----
    if (is64) {
        const long long* e = (const long long*)ei;
        for (int k = gtid; k < nE; k += NT) {
            int s = (int)e[k];
            int d = (int)e[nE + k];
            g_col[atomicAdd(&g_cursor[d], 1)] = s;
        }
    } else {
        const int* e = (const int*)ei;
        for (int k = gtid; k < nE; k += NT) {
            int s = e[k];
            int d = e[nE + k];
            g_col[atomicAdd(&g_cursor[d], 1)] = s;
        }
    }
    grid_sync();

    // ---- layers: cooperative gather + distributed dense update ----
    layer_phase<FF>(g_x,  Wrel1, b1, Wroot1, g_h1, n, sW, gtid);
    grid_sync();
    layer_phase<HH>(g_h1, Wrel2, b2, Wroot2, g_h2, n, sW, gtid);
    grid_sync();
    layer_phase<HH>(g_h2, Wrel3, b3, Wroot3, g_h1, n, sW, gtid);
    grid_sync();

    // ---- pool + readout ----
    pool_readout_phase(g_h1, batch, is64, Wlin, blin, out, n, ng, gtid);
}

// ---------------- launcher: ONE kernel launch ----------------------------
extern "C" void kernel_launch(void* const* d_in, const int* in_sizes, int n_in,
                              void* d_out, int out_size) {
    const float* x      = (const float*)d_in[0];
    const void*  ei     = d_in[1];
    const void*  batch  = d_in[2];
    const float* Wrel1  = (const float*)d_in[3];
    const float* b1     = (const float*)d_in[4];
    const float* Wroot1 = (const float*)d_in[5];
    const float* Wrel2  = (const float*)d_in[6];
    const float* b2     = (const float*)d_in[7];
    const float* Wroot2 = (const float*)d_in[8];
    const float* Wrel3  = (const float*)d_in[9];
    const float* b3     = (const float*)d_in[10];
    const float* Wroot3 = (const float*)d_in[11];
    const float* Wlin   = (const float*)d_in[12];
    const float* blin   = (const float*)d_in[13];

    const int n  = in_sizes[0] / FF;
    const int nE = in_sizes[1] / 2;
    const int ng = out_size / 2;

    fused_kernel<<<NBLK, NTHR>>>(x, ei, batch,
                                 Wrel1, b1, Wroot1,
                                 Wrel2, b2, Wroot2,
                                 Wrel3, b3, Wroot3,
                                 Wlin, blin, (float*)d_out, n, nE, ng);
}